// round 8
// baseline (speedup 1.0000x reference)
#include <cuda_runtime.h>
#include <cuda_bf16.h>

#define N_NODES 100000
#define IN_F 64
#define E_MAX 1600000

// Scratch
__device__ int g_deg[N_NODES];
__device__ int g_off[N_NODES];
__device__ int g_cursor[N_NODES];
__device__ int g_eidx[E_MAX];
__device__ int g_partials[512];
__device__ float g_y[(size_t)N_NODES * 64];   // y = x @ W_lin^T (25.6MB)

// Grid-barrier state (sense-reversing; replay-safe: cnt returns to 0, gen grows)
__device__ int g_bar_cnt;
__device__ volatile int g_bar_gen;

__device__ __forceinline__ void grid_bar(int nb) {
    __threadfence();
    __syncthreads();
    if (threadIdx.x == 0) {
        int gen = g_bar_gen;
        if (atomicAdd(&g_bar_cnt, 1) == nb - 1) {
            g_bar_cnt = 0;
            __threadfence();
            g_bar_gen = gen + 1;
        } else {
            while (g_bar_gen == gen) __nanosleep(32);
        }
    }
    __syncthreads();
}

// ---------------------------------------------------------------------------
// Packed f32x2 FMA (Blackwell FFMA2 — PTX only)
// ---------------------------------------------------------------------------
__device__ __forceinline__ unsigned long long fma_f32x2(unsigned long long a,
                                                        unsigned long long b,
                                                        unsigned long long c) {
    unsigned long long d;
    asm("fma.rn.f32x2 %0, %1, %2, %3;" : "=l"(d) : "l"(a), "l"(b), "l"(c));
    return d;
}
__device__ __forceinline__ unsigned long long pack_f32x2(float lo, float hi) {
    unsigned long long r;
    asm("mov.b64 %0, {%1, %2};" : "=l"(r) : "f"(lo), "f"(hi));
    return r;
}
__device__ __forceinline__ float sum_f32x2(unsigned long long v) {
    float lo, hi;
    asm("mov.b64 {%0, %1}, %2;" : "=f"(lo), "=f"(hi) : "l"(v));
    return lo + hi;
}

// ---------------------------------------------------------------------------
// K1: persistent CSR build, full grid, internal barriers.
// ---------------------------------------------------------------------------
__global__ void __launch_bounds__(256)
csr_build_kernel(const int* __restrict__ src,
                 const int* __restrict__ dst,
                 int N, int E, int nseg) {
    __shared__ int ib0[512];
    __shared__ int ib1[512];

    const int t = threadIdx.x;
    const int bid = blockIdx.x;
    const int grid = gridDim.x;

    // zero degrees
    for (int i = bid * 256 + t; i < N; i += grid * 256) g_deg[i] = 0;
    grid_bar(grid);

    // count in-degrees (non-returning reduction)
    for (int e = bid * 256 + t; e < E; e += grid * 256) {
        int* p = &g_deg[__ldg(dst + e)];
        asm volatile("red.global.add.s32 [%0], 1;" :: "l"(p) : "memory");
    }
    grid_bar(grid);

    // per-segment (256-wide) scans
    for (int s = bid; s < nseg; s += grid) {
        int i = s * 256 + t;
        int v = (i < N) ? g_deg[i] : 0;
        ib0[t] = v;
        __syncthreads();
        int* a = ib0; int* b = ib1;
        #pragma unroll
        for (int off = 1; off < 256; off <<= 1) {
            int sv = a[t];
            if (t >= off) sv += a[t - off];
            b[t] = sv;
            __syncthreads();
            int* tmp = a; a = b; b = tmp;
        }
        if (t == 255) g_partials[s] = a[255];
        if (i < N) g_off[i] = a[t] - v;   // exclusive within segment
        __syncthreads();
    }
    grid_bar(grid);

    // block 0: exclusive scan of nseg partials (nseg <= 512)
    if (bid == 0) {
        int v0 = (t < nseg) ? g_partials[t] : 0;
        int v1 = (t + 256 < nseg) ? g_partials[t + 256] : 0;
        ib0[t] = v0; ib0[t + 256] = v1;
        __syncthreads();
        int* a = ib0; int* b = ib1;
        #pragma unroll
        for (int off = 1; off < 512; off <<= 1) {
            int s0 = a[t];
            if (t >= off) s0 += a[t - off];
            int s1 = a[t + 256] + a[t + 256 - off];
            b[t] = s0; b[t + 256] = s1;
            __syncthreads();
            int* tmp = a; a = b; b = tmp;
        }
        if (t < nseg) g_partials[t] = a[t] - v0;
        if (t + 256 < nseg) g_partials[t + 256] = a[t + 256] - v1;
    }
    grid_bar(grid);

    // add segment bases; init cursors
    for (int s = bid; s < nseg; s += grid) {
        int base = g_partials[s];
        int i = s * 256 + t;
        if (i < N) {
            int sv = g_off[i] + base;
            g_off[i] = sv;
            g_cursor[i] = sv;
        }
    }
    grid_bar(grid);

    // fill buckets
    for (int e = bid * 256 + t; e < E; e += grid * 256) {
        int d = __ldg(dst + e);
        int pos = atomicAdd(&g_cursor[d], 1);
        g_eidx[pos] = __ldg(src + e);
    }
}

// ---------------------------------------------------------------------------
// K2: y = x @ W_lin^T ; out = x @ W_self^T + b  (independent of CSR)
// 256 threads: o = t&63, group g = t>>6, 8 nodes per thread, 32 nodes/tile.
// ---------------------------------------------------------------------------
__global__ void __launch_bounds__(256, 3)
gemm_kernel(const float* __restrict__ x,
            const float* __restrict__ W_lin,
            const float* __restrict__ b_lin,
            const float* __restrict__ W_self,
            const float* __restrict__ b_self,
            const float* __restrict__ bias,
            float* __restrict__ out,
            int N, int ntiles) {
    __shared__ float sWl[64 * 64];   // [f4][o][4]
    __shared__ float sWs[64 * 64];

    const int t = threadIdx.x;

    #pragma unroll
    for (int i = t; i < 64 * 64; i += 256) {
        int o = i >> 6;
        int f = i & 63;
        int dsti = (f >> 2) * 256 + o * 4 + (f & 3);
        sWl[dsti] = W_lin[i];
        sWs[dsti] = W_self[i];
    }
    __syncthreads();

    int o = t & 63;
    int g = t >> 6;
    float b = b_lin[o] + b_self[o] + bias[o];

    for (int tile = blockIdx.x; tile < ntiles; tile += gridDim.x) {
        int n0 = tile * 32 + g * 8;
        const float* __restrict__ xbase = x + (size_t)n0 * 64;

        if (n0 + 7 < N) {
            unsigned long long accY[8], accS[8];
            unsigned long long binit = pack_f32x2(b, 0.f);
            #pragma unroll
            for (int k = 0; k < 8; k++) { accY[k] = 0ull; accS[k] = binit; }

            #pragma unroll
            for (int f4 = 0; f4 < 16; f4++) {
                ulonglong2 wl = *reinterpret_cast<const ulonglong2*>(
                                    &sWl[f4 * 256 + o * 4]);
                ulonglong2 ws = *reinterpret_cast<const ulonglong2*>(
                                    &sWs[f4 * 256 + o * 4]);
                #pragma unroll
                for (int k = 0; k < 8; k++) {
                    ulonglong2 xv = *reinterpret_cast<const ulonglong2*>(
                                        xbase + k * 64 + f4 * 4);
                    accY[k] = fma_f32x2(xv.x, wl.x, accY[k]);
                    accY[k] = fma_f32x2(xv.y, wl.y, accY[k]);
                    accS[k] = fma_f32x2(xv.x, ws.x, accS[k]);
                    accS[k] = fma_f32x2(xv.y, ws.y, accS[k]);
                }
            }
            float* yp = g_y + (size_t)n0 * 64 + o;
            float* op = out + (size_t)n0 * 64 + o;
            #pragma unroll
            for (int k = 0; k < 8; k++) {
                yp[k * 64] = sum_f32x2(accY[k]);
                op[k * 64] = sum_f32x2(accS[k]);
            }
        } else {
            for (int k = 0; k < 8; k++) {
                int n = n0 + k;
                if (n >= N) break;
                float ay = 0.f, as = b;
                for (int f = 0; f < 64; f++) {
                    float xv = xbase[k * 64 + f];
                    ay += xv * sWl[(f >> 2) * 256 + o * 4 + (f & 3)];
                    as += xv * sWs[(f >> 2) * 256 + o * 4 + (f & 3)];
                }
                g_y[(size_t)n * 64 + o] = ay;
                out[(size_t)n * 64 + o] = as;
            }
        }
    }
}

// ---------------------------------------------------------------------------
// K3: gather: out[n] += sum_{e: dst[e]=n} y[src[e]].
// Reg-light, high occupancy (6 blocks/SM -> 48 warps) to hide L2 latency.
// 16 threads per node; 2 accumulators; 4 independent loads in flight.
// ---------------------------------------------------------------------------
__global__ void __launch_bounds__(256, 6)
gather_kernel(int N) {
    const float4* __restrict__ y4 = (const float4*)g_y;

    int idx = blockIdx.x * 256 + threadIdx.x;
    int node = idx >> 4;
    if (node >= N) return;
    int l = idx & 15;

    int beg = g_off[node];
    int cnt = g_deg[node];
    const int* __restrict__ ep = g_eidx + beg;

    float4 a0 = make_float4(0.f, 0.f, 0.f, 0.f);
    float4 a1 = a0;

    int j = 0;
    for (; j + 4 <= cnt; j += 4) {
        int s0 = __ldg(ep + j + 0);
        int s1 = __ldg(ep + j + 1);
        int s2 = __ldg(ep + j + 2);
        int s3 = __ldg(ep + j + 3);
        float4 v0 = __ldg(y4 + (size_t)s0 * 16 + l);
        float4 v1 = __ldg(y4 + (size_t)s1 * 16 + l);
        float4 v2 = __ldg(y4 + (size_t)s2 * 16 + l);
        float4 v3 = __ldg(y4 + (size_t)s3 * 16 + l);
        a0.x += v0.x; a0.y += v0.y; a0.z += v0.z; a0.w += v0.w;
        a1.x += v1.x; a1.y += v1.y; a1.z += v1.z; a1.w += v1.w;
        a0.x += v2.x; a0.y += v2.y; a0.z += v2.z; a0.w += v2.w;
        a1.x += v3.x; a1.y += v3.y; a1.z += v3.z; a1.w += v3.w;
    }
    for (; j < cnt; j++) {
        int s = __ldg(ep + j);
        float4 v = __ldg(y4 + (size_t)s * 16 + l);
        a0.x += v.x; a0.y += v.y; a0.z += v.z; a0.w += v.w;
    }

    // out[node] += a0 + a1  (out already holds x@Ws^T + b from K2)
    extern __shared__ char dummy[];  // (unused)
    float4* out4 = ((float4*)0);     // placeholder to silence type; real ptr via param below
    (void)out4; (void)dummy;
    // NOTE: out passed via global pointer param variant below
}

// Real gather with out pointer (the above stub replaced — keep one definition)
__global__ void __launch_bounds__(256, 6)
gather_out_kernel(float* __restrict__ out, int N) {
    const float4* __restrict__ y4 = (const float4*)g_y;
    float4* __restrict__ out4 = (float4*)out;

    int idx = blockIdx.x * 256 + threadIdx.x;
    int node = idx >> 4;
    if (node >= N) return;
    int l = idx & 15;

    int beg = g_off[node];
    int cnt = g_deg[node];
    const int* __restrict__ ep = g_eidx + beg;

    float4 a0 = make_float4(0.f, 0.f, 0.f, 0.f);
    float4 a1 = a0;

    int j = 0;
    for (; j + 4 <= cnt; j += 4) {
        int s0 = __ldg(ep + j + 0);
        int s1 = __ldg(ep + j + 1);
        int s2 = __ldg(ep + j + 2);
        int s3 = __ldg(ep + j + 3);
        float4 v0 = __ldg(y4 + (size_t)s0 * 16 + l);
        float4 v1 = __ldg(y4 + (size_t)s1 * 16 + l);
        float4 v2 = __ldg(y4 + (size_t)s2 * 16 + l);
        float4 v3 = __ldg(y4 + (size_t)s3 * 16 + l);
        a0.x += v0.x; a0.y += v0.y; a0.z += v0.z; a0.w += v0.w;
        a1.x += v1.x; a1.y += v1.y; a1.z += v1.z; a1.w += v1.w;
        a0.x += v2.x; a0.y += v2.y; a0.z += v2.z; a0.w += v2.w;
        a1.x += v3.x; a1.y += v3.y; a1.z += v3.z; a1.w += v3.w;
    }
    for (; j < cnt; j++) {
        int s = __ldg(ep + j);
        float4 v = __ldg(y4 + (size_t)s * 16 + l);
        a0.x += v.x; a0.y += v.y; a0.z += v.z; a0.w += v.w;
    }

    size_t oidx = (size_t)node * 16 + l;
    float4 cur = out4[oidx];
    cur.x += a0.x + a1.x;
    cur.y += a0.y + a1.y;
    cur.z += a0.z + a1.z;
    cur.w += a0.w + a1.w;
    out4[oidx] = cur;
}

// ---------------------------------------------------------------------------
// Launch. Input order: x, src, dst, W_lin, b_lin, W_self, b_self, bias
// ---------------------------------------------------------------------------
extern "C" void kernel_launch(void* const* d_in, const int* in_sizes, int n_in,
                              void* d_out, int out_size) {
    const float* x      = (const float*)d_in[0];
    const int*   src    = (const int*)d_in[1];
    const int*   dst    = (const int*)d_in[2];
    const float* W_lin  = (const float*)d_in[3];
    const float* b_lin  = (const float*)d_in[4];
    const float* W_self = (const float*)d_in[5];
    const float* b_self = (const float*)d_in[6];
    const float* bias   = (const float*)d_in[7];
    float* out = (float*)d_out;

    int N = in_sizes[0] / IN_F;   // 100000
    int E = in_sizes[1];          // 1280000
    int nseg = (N + 255) / 256;   // 391 (<=512)
    int ntiles = (N + 31) / 32;   // 3125

    int dev = 0, sms = 148, occ1 = 4;
    cudaGetDevice(&dev);
    cudaDeviceGetAttribute(&sms, cudaDevAttrMultiProcessorCount, dev);

    // K1: persistent CSR build — deadlock-safe grid
    cudaOccupancyMaxActiveBlocksPerMultiprocessor(&occ1, csr_build_kernel, 256, 0);
    int g1 = sms * occ1;
    if (g1 > 1024) g1 = 1024;
    if (g1 < 1) g1 = 1;
    csr_build_kernel<<<g1, 256>>>(src, dst, N, E, nseg);

    // K2: GEMM (y and out self-term)
    int g2 = sms * 3;
    if (g2 > ntiles) g2 = ntiles;
    gemm_kernel<<<g2, 256>>>(x, W_lin, b_lin, W_self, b_self, bias, out,
                             N, ntiles);

    // K3: gather into out
    long long gt = (long long)N * 16;
    gather_out_kernel<<<(int)((gt + 255) / 256), 256>>>(out, N);
}

// round 9
// speedup vs baseline: 1.3983x; 1.3983x over previous
#include <cuda_runtime.h>
#include <cuda_bf16.h>

#define N_NODES 100000
#define IN_F 64
#define E_MAX 1600000
#define NREP 4

// Scratch
__device__ int g_degR[NREP * N_NODES];   // replicated degree counters
__device__ int g_curR[NREP * N_NODES];   // replicated fill cursors
__device__ int g_deg[N_NODES];           // total degree
__device__ int g_off[N_NODES];           // CSR offsets
__device__ int g_eidx[E_MAX];            // src per edge, bucketed by dst
__device__ int g_partials[512];
__device__ float g_y[(size_t)N_NODES * 64];   // y = x @ W_lin^T (25.6MB)

// Grid barrier (sense-reversing, replay-safe: cnt returns to 0, gen grows)
__device__ int g_bar_cnt;
__device__ volatile int g_bar_gen;

__device__ __forceinline__ void grid_bar(int nb) {
    __threadfence();
    __syncthreads();
    if (threadIdx.x == 0) {
        int gen = g_bar_gen;
        if (atomicAdd(&g_bar_cnt, 1) == nb - 1) {
            g_bar_cnt = 0;
            __threadfence();
            g_bar_gen = gen + 1;
        } else {
            while (g_bar_gen == gen) __nanosleep(32);
        }
    }
    __syncthreads();
}

// ---------------------------------------------------------------------------
// Packed f32x2 FMA (Blackwell FFMA2 — PTX only)
// ---------------------------------------------------------------------------
__device__ __forceinline__ unsigned long long fma_f32x2(unsigned long long a,
                                                        unsigned long long b,
                                                        unsigned long long c) {
    unsigned long long d;
    asm("fma.rn.f32x2 %0, %1, %2, %3;" : "=l"(d) : "l"(a), "l"(b), "l"(c));
    return d;
}
__device__ __forceinline__ unsigned long long pack_f32x2(float lo, float hi) {
    unsigned long long r;
    asm("mov.b64 %0, {%1, %2};" : "=l"(r) : "f"(lo), "f"(hi));
    return r;
}
__device__ __forceinline__ float sum_f32x2(unsigned long long v) {
    float lo, hi;
    asm("mov.b64 {%0, %1}, %2;" : "=f"(lo), "=f"(hi) : "l"(v));
    return lo + hi;
}

// ---------------------------------------------------------------------------
// K1: persistent CSR build with 4-way replicated atomics.
// Replica r = (bid ^ (t>>5)) & 3 — identical mapping in count and fill, so
// each edge hits the same replica in both passes and slot ranges line up.
// ---------------------------------------------------------------------------
__global__ void __launch_bounds__(256)
csr_build_kernel(const int* __restrict__ src,
                 const int* __restrict__ dst,
                 int N, int E, int nseg) {
    __shared__ int ib0[512];
    __shared__ int ib1[512];

    const int t = threadIdx.x;
    const int bid = blockIdx.x;
    const int grid = gridDim.x;
    const int r = (bid ^ (t >> 5)) & (NREP - 1);

    // zero replicated degree counters
    for (int i = bid * 256 + t; i < NREP * N; i += grid * 256) g_degR[i] = 0;
    grid_bar(grid);

    // count in-degrees into replica r (non-returning reduction)
    {
        int* degr = g_degR + r * N;
        for (int e = bid * 256 + t; e < E; e += grid * 256) {
            int* p = degr + __ldg(dst + e);
            asm volatile("red.global.add.s32 [%0], 1;" :: "l"(p) : "memory");
        }
    }
    grid_bar(grid);

    // per-segment (256-wide) scans over total degree
    for (int s = bid; s < nseg; s += grid) {
        int i = s * 256 + t;
        int v = 0;
        if (i < N) {
            v = g_degR[i] + g_degR[N + i] + g_degR[2 * N + i]
              + g_degR[3 * N + i];
            g_deg[i] = v;
        }
        ib0[t] = v;
        __syncthreads();
        int* a = ib0; int* b = ib1;
        #pragma unroll
        for (int off = 1; off < 256; off <<= 1) {
            int sv = a[t];
            if (t >= off) sv += a[t - off];
            b[t] = sv;
            __syncthreads();
            int* tmp = a; a = b; b = tmp;
        }
        if (t == 255) g_partials[s] = a[255];
        if (i < N) g_off[i] = a[t] - v;   // exclusive within segment
        __syncthreads();
    }
    grid_bar(grid);

    // block 0: exclusive scan of nseg partials (nseg <= 512)
    if (bid == 0) {
        int v0 = (t < nseg) ? g_partials[t] : 0;
        int v1 = (t + 256 < nseg) ? g_partials[t + 256] : 0;
        ib0[t] = v0; ib0[t + 256] = v1;
        __syncthreads();
        int* a = ib0; int* b = ib1;
        #pragma unroll
        for (int off = 1; off < 512; off <<= 1) {
            int s0 = a[t];
            if (t >= off) s0 += a[t - off];
            int s1 = a[t + 256] + a[t + 256 - off];
            b[t] = s0; b[t + 256] = s1;
            __syncthreads();
            int* tmp = a; a = b; b = tmp;
        }
        if (t < nseg) g_partials[t] = a[t] - v0;
        if (t + 256 < nseg) g_partials[t + 256] = a[t + 256] - v1;
    }
    grid_bar(grid);

    // add segment bases; derive per-replica cursor bases
    for (int s = bid; s < nseg; s += grid) {
        int base = g_partials[s];
        int i = s * 256 + t;
        if (i < N) {
            int off = g_off[i] + base;
            g_off[i] = off;
            int c0 = off;
            int c1 = c0 + g_degR[i];
            int c2 = c1 + g_degR[N + i];
            int c3 = c2 + g_degR[2 * N + i];
            g_curR[i] = c0;
            g_curR[N + i] = c1;
            g_curR[2 * N + i] = c2;
            g_curR[3 * N + i] = c3;
        }
    }
    grid_bar(grid);

    // fill buckets via replica-r cursor
    {
        int* curr = g_curR + r * N;
        for (int e = bid * 256 + t; e < E; e += grid * 256) {
            int d = __ldg(dst + e);
            int pos = atomicAdd(curr + d, 1);
            g_eidx[pos] = __ldg(src + e);
        }
    }
}

// ---------------------------------------------------------------------------
// K2: y = x @ W_lin^T ; out = x @ W_self^T + b  (independent of CSR)
// ---------------------------------------------------------------------------
__global__ void __launch_bounds__(256, 3)
gemm_kernel(const float* __restrict__ x,
            const float* __restrict__ W_lin,
            const float* __restrict__ b_lin,
            const float* __restrict__ W_self,
            const float* __restrict__ b_self,
            const float* __restrict__ bias,
            float* __restrict__ out,
            int N, int ntiles) {
    __shared__ float sWl[64 * 64];   // [f4][o][4]
    __shared__ float sWs[64 * 64];

    const int t = threadIdx.x;

    #pragma unroll
    for (int i = t; i < 64 * 64; i += 256) {
        int o = i >> 6;
        int f = i & 63;
        int dsti = (f >> 2) * 256 + o * 4 + (f & 3);
        sWl[dsti] = W_lin[i];
        sWs[dsti] = W_self[i];
    }
    __syncthreads();

    int o = t & 63;
    int g = t >> 6;
    float b = b_lin[o] + b_self[o] + bias[o];

    for (int tile = blockIdx.x; tile < ntiles; tile += gridDim.x) {
        int n0 = tile * 32 + g * 8;
        const float* __restrict__ xbase = x + (size_t)n0 * 64;

        if (n0 + 7 < N) {
            unsigned long long accY[8], accS[8];
            unsigned long long binit = pack_f32x2(b, 0.f);
            #pragma unroll
            for (int k = 0; k < 8; k++) { accY[k] = 0ull; accS[k] = binit; }

            #pragma unroll
            for (int f4 = 0; f4 < 16; f4++) {
                ulonglong2 wl = *reinterpret_cast<const ulonglong2*>(
                                    &sWl[f4 * 256 + o * 4]);
                ulonglong2 ws = *reinterpret_cast<const ulonglong2*>(
                                    &sWs[f4 * 256 + o * 4]);
                #pragma unroll
                for (int k = 0; k < 8; k++) {
                    ulonglong2 xv = *reinterpret_cast<const ulonglong2*>(
                                        xbase + k * 64 + f4 * 4);
                    accY[k] = fma_f32x2(xv.x, wl.x, accY[k]);
                    accY[k] = fma_f32x2(xv.y, wl.y, accY[k]);
                    accS[k] = fma_f32x2(xv.x, ws.x, accS[k]);
                    accS[k] = fma_f32x2(xv.y, ws.y, accS[k]);
                }
            }
            float* yp = g_y + (size_t)n0 * 64 + o;
            float* op = out + (size_t)n0 * 64 + o;
            #pragma unroll
            for (int k = 0; k < 8; k++) {
                yp[k * 64] = sum_f32x2(accY[k]);
                op[k * 64] = sum_f32x2(accS[k]);
            }
        } else {
            for (int k = 0; k < 8; k++) {
                int n = n0 + k;
                if (n >= N) break;
                float ay = 0.f, as = b;
                for (int f = 0; f < 64; f++) {
                    float xv = xbase[k * 64 + f];
                    ay += xv * sWl[(f >> 2) * 256 + o * 4 + (f & 3)];
                    as += xv * sWs[(f >> 2) * 256 + o * 4 + (f & 3)];
                }
                g_y[(size_t)n * 64 + o] = ay;
                out[(size_t)n * 64 + o] = as;
            }
        }
    }
}

// ---------------------------------------------------------------------------
// K3: gather: out[n] += sum_{e: dst[e]=n} y[src[e]].
// 16 threads per node, 4-edge unroll (MLP=4). (256,4) -> 64-reg budget:
// NO spills (the R8 (256,6) variant spilled and was 2-3x slower).
// ---------------------------------------------------------------------------
__global__ void __launch_bounds__(256, 4)
gather_out_kernel(float* __restrict__ out, int N) {
    const float4* __restrict__ y4 = (const float4*)g_y;
    float4* __restrict__ out4 = (float4*)out;

    int idx = blockIdx.x * 256 + threadIdx.x;
    int node = idx >> 4;
    if (node >= N) return;
    int l = idx & 15;

    int beg = g_off[node];
    int cnt = g_deg[node];
    const int* __restrict__ ep = g_eidx + beg;

    float4 a0 = make_float4(0.f, 0.f, 0.f, 0.f);
    float4 a1 = a0;

    int j = 0;
    for (; j + 4 <= cnt; j += 4) {
        int s0 = __ldg(ep + j + 0);
        int s1 = __ldg(ep + j + 1);
        int s2 = __ldg(ep + j + 2);
        int s3 = __ldg(ep + j + 3);
        float4 v0 = __ldg(y4 + (size_t)s0 * 16 + l);
        float4 v1 = __ldg(y4 + (size_t)s1 * 16 + l);
        float4 v2 = __ldg(y4 + (size_t)s2 * 16 + l);
        float4 v3 = __ldg(y4 + (size_t)s3 * 16 + l);
        a0.x += v0.x; a0.y += v0.y; a0.z += v0.z; a0.w += v0.w;
        a1.x += v1.x; a1.y += v1.y; a1.z += v1.z; a1.w += v1.w;
        a0.x += v2.x; a0.y += v2.y; a0.z += v2.z; a0.w += v2.w;
        a1.x += v3.x; a1.y += v3.y; a1.z += v3.z; a1.w += v3.w;
    }
    for (; j < cnt; j++) {
        int s = __ldg(ep + j);
        float4 v = __ldg(y4 + (size_t)s * 16 + l);
        a0.x += v.x; a0.y += v.y; a0.z += v.z; a0.w += v.w;
    }

    size_t oidx = (size_t)node * 16 + l;
    float4 cur = out4[oidx];
    cur.x += a0.x + a1.x;
    cur.y += a0.y + a1.y;
    cur.z += a0.z + a1.z;
    cur.w += a0.w + a1.w;
    out4[oidx] = cur;
}

// ---------------------------------------------------------------------------
// Launch. Input order: x, src, dst, W_lin, b_lin, W_self, b_self, bias
// ---------------------------------------------------------------------------
extern "C" void kernel_launch(void* const* d_in, const int* in_sizes, int n_in,
                              void* d_out, int out_size) {
    const float* x      = (const float*)d_in[0];
    const int*   src    = (const int*)d_in[1];
    const int*   dst    = (const int*)d_in[2];
    const float* W_lin  = (const float*)d_in[3];
    const float* b_lin  = (const float*)d_in[4];
    const float* W_self = (const float*)d_in[5];
    const float* b_self = (const float*)d_in[6];
    const float* bias   = (const float*)d_in[7];
    float* out = (float*)d_out;

    int N = in_sizes[0] / IN_F;   // 100000
    int E = in_sizes[1];          // 1280000
    int nseg = (N + 255) / 256;   // 391 (<=512)
    int ntiles = (N + 31) / 32;   // 3125

    int dev = 0, sms = 148, occ1 = 4;
    cudaGetDevice(&dev);
    cudaDeviceGetAttribute(&sms, cudaDevAttrMultiProcessorCount, dev);

    // K1: persistent CSR build — deadlock-safe grid
    cudaOccupancyMaxActiveBlocksPerMultiprocessor(&occ1, csr_build_kernel, 256, 0);
    if (occ1 > 4) occ1 = 4;       // 592 blocks max: keeps barrier straggle low
    if (occ1 < 1) occ1 = 1;
    int g1 = sms * occ1;
    csr_build_kernel<<<g1, 256>>>(src, dst, N, E, nseg);

    // K2: GEMM (y and out self-term)
    int g2 = sms * 3;
    if (g2 > ntiles) g2 = ntiles;
    gemm_kernel<<<g2, 256>>>(x, W_lin, b_lin, W_self, b_self, bias, out,
                             N, ntiles);

    // K3: gather into out
    long long gt = (long long)N * 16;
    gather_out_kernel<<<(int)((gt + 255) / 256), 256>>>(out, N);
}